// round 11
// baseline (speedup 1.0000x reference)
#include <cuda_runtime.h>
#include <cuda_bf16.h>
#include <cstdint>

// Problem constants
#define BATCH 32
#define SEQ   256
#define HID   1024
#define HL    512
#define EOUT  256
#define NLANG 5

typedef unsigned long long ull;

// ---------------------------------------------------------------------------
// Scratch (device globals — no allocation allowed)
// ---------------------------------------------------------------------------
__device__ float g_h1[BATCH * SEQ * HID];
__device__ float g_adapted[BATCH * SEQ * HID];
__device__ float g_gates_f[BATCH * SEQ * 4 * HL];
__device__ float g_gates_b[BATCH * SEQ * 4 * HL];
__device__ float g_ys[BATCH * SEQ * 2 * HL];
__device__ float g_h[2][2][HL][BATCH];     // dir, pingpong, UNIT, BATCH
__device__ unsigned g_bar[2];
__device__ int   g_lang[BATCH];
__device__ float g_Wt1[NLANG * HID * HID];
__device__ float g_Wt2[NLANG * HID * HID];

// ---------------------------------------------------------------------------
// tf32 split + mma.sync helpers
// ---------------------------------------------------------------------------
__device__ __forceinline__ void tf32_split(float x, uint32_t& hi, uint32_t& lo)
{
    uint32_t h;
    asm("cvt.rna.tf32.f32 %0, %1;" : "=r"(h) : "f"(x));
    float r = x - __uint_as_float(h);
    uint32_t l;
    asm("cvt.rna.tf32.f32 %0, %1;" : "=r"(l) : "f"(r));
    hi = h; lo = l;
}

__device__ __forceinline__ void mma8(float* d, const uint32_t* a, const uint32_t* b)
{
    asm volatile(
        "mma.sync.aligned.m16n8k8.row.col.f32.tf32.tf32.f32 "
        "{%0,%1,%2,%3}, {%4,%5,%6,%7}, {%8,%9}, {%0,%1,%2,%3};"
        : "+f"(d[0]), "+f"(d[1]), "+f"(d[2]), "+f"(d[3])
        : "r"(a[0]), "r"(a[1]), "r"(a[2]), "r"(a[3]), "r"(b[0]), "r"(b[1]));
}

__device__ __forceinline__ void ffma2(ull& d, ull a, ull b)
{
    asm("fma.rn.f32x2 %0, %1, %2, %0;" : "+l"(d) : "l"(a), "l"(b));
}

// ---------------------------------------------------------------------------
// 3xtf32 NT GEMM body: C[128,128] = A[128,K] @ B[128,K]^T + bias
// 512 threads, 16 warps (8 along M x 2 along N), warp tile 16x64.
// ---------------------------------------------------------------------------
#define BKC 16
#define MM_PAD 136

__device__ __forceinline__ void mma_nt_body(
    const float* __restrict__ At, int lda,
    const float* __restrict__ Bt, int ldb,
    const float* __restrict__ bias_t,
    float* __restrict__ Ct, int ldc,
    int K)
{
    __shared__ uint32_t As_hi[BKC][MM_PAD], As_lo[BKC][MM_PAD];
    __shared__ uint32_t Bs_hi[BKC][MM_PAD], Bs_lo[BKC][MM_PAD];

    int tid = threadIdx.x;
    int lane = tid & 31, wid = tid >> 5;
    int warpM = wid & 7, warpN = wid >> 3;
    int m0 = warpM * 16, n0w = warpN * 64;
    int g = lane >> 2, t4 = lane & 3;

    // staging ownership: thread t loads one float4 of A and one of B
    int r = tid >> 2, kq = (tid & 3) * 4;

    float acc[8][4];
#pragma unroll
    for (int ni = 0; ni < 8; ni++)
#pragma unroll
        for (int q = 0; q < 4; q++) acc[ni][q] = 0.f;

    float4 pa = *(const float4*)(At + (size_t)r * lda + kq);
    float4 pb = *(const float4*)(Bt + (size_t)r * ldb + kq);

    int nch = K >> 4;
    for (int c = 0; c < nch; ++c) {
        __syncthreads();
        {
            float av[4] = {pa.x, pa.y, pa.z, pa.w};
            float bv[4] = {pb.x, pb.y, pb.z, pb.w};
#pragma unroll
            for (int i = 0; i < 4; i++) {
                uint32_t h, l;
                tf32_split(av[i], h, l);
                As_hi[kq + i][r] = h; As_lo[kq + i][r] = l;
                tf32_split(bv[i], h, l);
                Bs_hi[kq + i][r] = h; Bs_lo[kq + i][r] = l;
            }
        }
        __syncthreads();
        if (c + 1 < nch) {
            int k0 = (c + 1) * BKC;
            pa = *(const float4*)(At + (size_t)r * lda + k0 + kq);
            pb = *(const float4*)(Bt + (size_t)r * ldb + k0 + kq);
        }
#pragma unroll
        for (int ks = 0; ks < BKC; ks += 8) {
            uint32_t ah[4], al[4];
            ah[0] = As_hi[ks + t4][m0 + g];
            ah[1] = As_hi[ks + t4][m0 + g + 8];
            ah[2] = As_hi[ks + t4 + 4][m0 + g];
            ah[3] = As_hi[ks + t4 + 4][m0 + g + 8];
            al[0] = As_lo[ks + t4][m0 + g];
            al[1] = As_lo[ks + t4][m0 + g + 8];
            al[2] = As_lo[ks + t4 + 4][m0 + g];
            al[3] = As_lo[ks + t4 + 4][m0 + g + 8];
#pragma unroll
            for (int ni = 0; ni < 8; ni++) {
                int n = n0w + ni * 8 + g;
                uint32_t bh[2], bl[2];
                bh[0] = Bs_hi[ks + t4][n];
                bh[1] = Bs_hi[ks + t4 + 4][n];
                bl[0] = Bs_lo[ks + t4][n];
                bl[1] = Bs_lo[ks + t4 + 4][n];
                mma8(acc[ni], ah, bh);
                mma8(acc[ni], ah, bl);
                mma8(acc[ni], al, bh);
            }
        }
    }

#pragma unroll
    for (int ni = 0; ni < 8; ni++) {
        int row0 = m0 + g;
        int col = n0w + ni * 8 + 2 * t4;
        float2 b2 = *(const float2*)&bias_t[col];
        float2 o0 = {acc[ni][0] + b2.x, acc[ni][1] + b2.y};
        float2 o1 = {acc[ni][2] + b2.x, acc[ni][3] + b2.y};
        *(float2*)&Ct[(size_t)row0 * ldc + col] = o0;
        *(float2*)&Ct[(size_t)(row0 + 8) * ldc + col] = o1;
    }
}

__global__ void __launch_bounds__(512) mma_adapter_kernel(
    const float* __restrict__ Abase, const float* __restrict__ Wt,
    const float* __restrict__ ball, float* __restrict__ Cbase)
{
    int b = blockIdx.z;
    int l = g_lang[b];
    const float* At = Abase + (size_t)b * SEQ * HID + (size_t)blockIdx.y * 128 * HID;
    const float* Bt = Wt + (size_t)l * HID * HID + (size_t)blockIdx.x * 128 * HID;
    const float* bias_t = ball + (size_t)l * HID + blockIdx.x * 128;
    float* Ct = Cbase + (size_t)b * SEQ * HID + (size_t)blockIdx.y * 128 * HID
              + blockIdx.x * 128;
    mma_nt_body(At, HID, Bt, HID, bias_t, Ct, HID, HID);
}

__global__ void __launch_bounds__(512) mma_nt_kernel(
    const float* __restrict__ A, const float* __restrict__ B,
    const float* __restrict__ bias, float* __restrict__ C, int K, int ldc)
{
    const float* At = A + (size_t)blockIdx.y * 128 * K;
    const float* Bt = B + (size_t)blockIdx.x * 128 * K;
    const float* bias_t = bias + blockIdx.x * 128;
    float* Ct = C + (size_t)blockIdx.y * 128 * ldc + blockIdx.x * 128;
    mma_nt_body(At, K, Bt, K, bias_t, Ct, ldc, K);
}

// ---------------------------------------------------------------------------
// W transpose: Wt[l][n][k] = W[l][k][n]
// ---------------------------------------------------------------------------
__global__ void __launch_bounds__(256) transpose_w_kernel(
    const float* __restrict__ W, float* __restrict__ Wt)
{
    __shared__ float tile[32][33];
    int l = blockIdx.z;
    int k0 = blockIdx.y * 32, n0 = blockIdx.x * 32;
    const float* Win = W + (size_t)l * HID * HID;
    float* Wout = Wt + (size_t)l * HID * HID;
    int x = threadIdx.x & 31, y = (threadIdx.x >> 5) * 4;
#pragma unroll
    for (int i = 0; i < 4; i++)
        tile[y + i][x] = Win[(size_t)(k0 + y + i) * HID + n0 + x];
    __syncthreads();
#pragma unroll
    for (int i = 0; i < 4; i++)
        Wout[(size_t)(n0 + y + i) * HID + k0 + x] = tile[x][y + i];
}

// ---------------------------------------------------------------------------
// Language-id normalization (dtype-robust)
// ---------------------------------------------------------------------------
__global__ void lang_normalize_kernel(const int* __restrict__ raw)
{
    __shared__ int first[32];
    int t = threadIdx.x;
    first[t] = raw[t];
    __syncwarp();
    bool odd_zero = true;
#pragma unroll
    for (int i = 1; i < 32; i += 2) odd_zero &= (first[i] == 0);
    int v = odd_zero ? raw[2 * t] : first[t];
    v = v < 0 ? 0 : (v >= NLANG ? NLANG - 1 : v);
    g_lang[t] = v;
}

// ---------------------------------------------------------------------------
// fp32 SIMT NT GEMM (projection only)
// ---------------------------------------------------------------------------
#define TS_BM 128
#define TS_BN 64
#define TS_BK 16

__global__ void __launch_bounds__(256) nt_gemm_kernel(
    const float* __restrict__ A, const float* __restrict__ Bm,
    const float* __restrict__ bias, float* __restrict__ C,
    int K, int ldc)
{
    __shared__ float As[TS_BK][TS_BM + 4];
    __shared__ float Bs[TS_BK][TS_BN];
    int row0 = blockIdx.y * TS_BM, col0 = blockIdx.x * TS_BN;
    int tid = threadIdx.x;
    int tx = tid & 15, ty = tid >> 4;
    float acc[8][4];
#pragma unroll
    for (int i = 0; i < 8; i++)
#pragma unroll
        for (int j = 0; j < 4; j++) acc[i][j] = 0.f;

    for (int k0 = 0; k0 < K; k0 += TS_BK) {
#pragma unroll
        for (int q = 0; q < 2; ++q) {
            int slot = tid + q * 256;
            int rr = slot >> 2;
            int kk = (slot & 3) * 4;
            float4 v = *(const float4*)&A[(size_t)(row0 + rr) * K + k0 + kk];
            As[kk + 0][rr] = v.x; As[kk + 1][rr] = v.y;
            As[kk + 2][rr] = v.z; As[kk + 3][rr] = v.w;
        }
        {
            int n = tid >> 2;
            int kk4 = (tid & 3) * 4;
            float4 v = *(const float4*)&Bm[(size_t)(col0 + n) * K + k0 + kk4];
            Bs[kk4 + 0][n] = v.x; Bs[kk4 + 1][n] = v.y;
            Bs[kk4 + 2][n] = v.z; Bs[kk4 + 3][n] = v.w;
        }
        __syncthreads();
#pragma unroll
        for (int kk = 0; kk < TS_BK; ++kk) {
            float a[8];
#pragma unroll
            for (int i = 0; i < 8; i++) a[i] = As[kk][ty * 8 + i];
            float4 bv = *(const float4*)&Bs[kk][tx * 4];
#pragma unroll
            for (int i = 0; i < 8; i++) {
                acc[i][0] += a[i] * bv.x; acc[i][1] += a[i] * bv.y;
                acc[i][2] += a[i] * bv.z; acc[i][3] += a[i] * bv.w;
            }
        }
        __syncthreads();
    }
    float4 bb = *(const float4*)&bias[col0 + tx * 4];
#pragma unroll
    for (int i = 0; i < 8; i++) {
        float4 o;
        o.x = acc[i][0] + bb.x; o.y = acc[i][1] + bb.y;
        o.z = acc[i][2] + bb.z; o.w = acc[i][3] + bb.w;
        *(float4*)&C[(size_t)(row0 + ty * 8 + i) * ldc + col0 + tx * 4] = o;
    }
}

// ---------------------------------------------------------------------------
// LayerNorm (biased var) + ReLU, in place
// ---------------------------------------------------------------------------
__global__ void __launch_bounds__(256) ln_relu_kernel(
    float* __restrict__ h, const float* __restrict__ ln_g_all,
    const float* __restrict__ ln_b_all)
{
    int row = blockIdx.x;
    int b = row >> 8;
    int l = g_lang[b];
    float4* x = (float4*)(h + (size_t)row * HID);
    float4 v = x[threadIdx.x];
    float s = v.x + v.y + v.z + v.w;
    float ss = v.x * v.x + v.y * v.y + v.z * v.z + v.w * v.w;
#pragma unroll
    for (int o = 16; o; o >>= 1) {
        s += __shfl_xor_sync(0xffffffffu, s, o);
        ss += __shfl_xor_sync(0xffffffffu, ss, o);
    }
    __shared__ float rs[8], rss[8];
    __shared__ float smean, sinv;
    int w = threadIdx.x >> 5;
    if ((threadIdx.x & 31) == 0) { rs[w] = s; rss[w] = ss; }
    __syncthreads();
    if (threadIdx.x == 0) {
        float S = 0.f, SS = 0.f;
#pragma unroll
        for (int i = 0; i < 8; i++) { S += rs[i]; SS += rss[i]; }
        float mean = S * (1.f / 1024.f);
        float var = SS * (1.f / 1024.f) - mean * mean;
        smean = mean;
        sinv = rsqrtf(var + 1e-5f);
    }
    __syncthreads();
    float mean = smean, inv = sinv;
    float4 g4 = *((const float4*)(ln_g_all + (size_t)l * HID) + threadIdx.x);
    float4 b4 = *((const float4*)(ln_b_all + (size_t)l * HID) + threadIdx.x);
    v.x = fmaxf((v.x - mean) * inv * g4.x + b4.x, 0.f);
    v.y = fmaxf((v.y - mean) * inv * g4.y + b4.y, 0.f);
    v.z = fmaxf((v.z - mean) * inv * g4.z + b4.z, 0.f);
    v.w = fmaxf((v.w - mean) * inv * g4.w + b4.w, 0.f);
    x[threadIdx.x] = v;
}

// ---------------------------------------------------------------------------
// Persistent BiLSTM — register-resident Whh + broadcast h + warp-local staging.
// Warp w stages ONLY its own k-segment of h (rows [64w,64w+64)) -> __syncwarp
// instead of a block-wide barrier between staging and compute.
// ---------------------------------------------------------------------------
#define LSTM_HS_FLOATS (512 * 32)                 // 64 KB
#define LSTM_GS_FLOATS (8 * 32 * 36)              // 36 KB
#define LSTM_SMEM_BYTES ((LSTM_HS_FLOATS + LSTM_GS_FLOATS) * 4)

__device__ __forceinline__ float sigf(float x) { return 1.f / (1.f + expf(-x)); }

__global__ void __launch_bounds__(256, 1) lstm_kernel(
    const float* __restrict__ gates_f, const float* __restrict__ gates_b,
    const float* __restrict__ Whh_fw, const float* __restrict__ Whh_bw,
    const int* __restrict__ mask, float* __restrict__ ys)
{
    extern __shared__ float sm[];
    float* hs = sm;                                // [512][32]
    float* gsm = sm + LSTM_HS_FLOATS;              // [8][32][36]

    int tid = threadIdx.x;
    int dir = blockIdx.y;
    int u0 = blockIdx.x * 8;
    const float* Whh = dir ? Whh_bw : Whh_fw;
    const float* G = dir ? gates_b : gates_f;

    int lane = tid & 31, wp = tid >> 5;
    int grow = (lane >> 3) * HL + u0 + (lane & 7);
    int ks = wp * 64;

    // Register-resident Whh segment (persistent across all steps)
    float w_reg[64];
    {
        const float4* wsrc = (const float4*)(Whh + (size_t)grow * HL + ks);
#pragma unroll
        for (int j = 0; j < 16; j++) {
            float4 v = wsrc[j];
            w_reg[4 * j + 0] = v.x; w_reg[4 * j + 1] = v.y;
            w_reg[4 * j + 2] = v.z; w_reg[4 * j + 3] = v.w;
        }
    }

    int cu = tid >> 5;       // 0..7
    int cb = tid & 31;       // 0..31
    float c = 0.f;

    float* grow_out = gsm + (wp * 32 + lane) * 36;
    float4* hdst_seg = (float4*)(hs + ks * 32);    // this warp's 512 float4

    for (int t = 0; t < SEQ; ++t) {
        int s = dir ? (SEQ - 1 - t) : t;
        int pp = t & 1;

        size_t gbase = ((size_t)(cb * SEQ + s)) * (4 * HL) + u0 + cu;
        float gi = G[gbase];
        float gf = G[gbase + 512];
        float gg = G[gbase + 1024];
        float go = G[gbase + 1536];
        int m = mask[cb * SEQ + s];

        // Warp-local staging: rows [ks, ks+64) = 512 float4, 16 per lane
        {
            const float4* hsrc = (const float4*)(&g_h[dir][pp][0][0]) + ks * 8;
#pragma unroll
            for (int i = 0; i < 16; ++i)
                hdst_seg[lane + 32 * i] = __ldcg(hsrc + lane + 32 * i);
        }
        __syncwarp();

        // Broadcast GEMM: this lane's gate-row x 32 batches over its 64 k
        ull acc[16];
#pragma unroll
        for (int j = 0; j < 16; j++) acc[j] = 0ull;
#pragma unroll
        for (int k = 0; k < 64; ++k) {
            uint32_t wb = __float_as_uint(w_reg[k]);
            ull w2;
            asm("mov.b64 %0, {%1, %1};" : "=l"(w2) : "r"(wb));
            const ulonglong2* hp = (const ulonglong2*)(hs + (ks + k) * 32);
#pragma unroll
            for (int j = 0; j < 8; ++j) {
                ulonglong2 h2 = hp[j];
                ffma2(acc[2 * j], w2, h2.x);
                ffma2(acc[2 * j + 1], w2, h2.y);
            }
        }
#pragma unroll
        for (int j = 0; j < 8; ++j) {
            ulonglong2 o;
            o.x = acc[2 * j]; o.y = acc[2 * j + 1];
            *(ulonglong2*)(grow_out + 4 * j) = o;
        }
        __syncthreads();

        // Cell update: sum 8 k-segment partials per gate
        {
            float ii = gi, ff = gf, g2 = gg, oo = go;
#pragma unroll
            for (int w = 0; w < 8; ++w) {
                const float* base = gsm + w * (32 * 36) + cb;
                ii += base[(0 * 8 + cu) * 36];
                ff += base[(1 * 8 + cu) * 36];
                g2 += base[(2 * 8 + cu) * 36];
                oo += base[(3 * 8 + cu) * 36];
            }
            float cn = sigf(ff) * c + sigf(ii) * tanhf(g2);
            float hn = sigf(oo) * tanhf(cn);
            float hold = hs[(u0 + cu) * 32 + cb];
            float hw = m ? hn : hold;
            c = m ? cn : c;
            g_h[dir][1 - pp][u0 + cu][cb] = hw;
            ys[((size_t)(cb * SEQ + s)) * (2 * HL) + dir * HL + u0 + cu] = m ? hn : 0.f;
        }

        // Per-direction grid barrier (64 blocks), tight spin
        __syncthreads();
        if (tid == 0) {
            __threadfence();
            atomicAdd(&g_bar[dir], 1u);
            unsigned tgt = 64u * (unsigned)(t + 1);
            while (*(volatile unsigned*)&g_bar[dir] < tgt) { }
            __threadfence();
        }
        __syncthreads();
    }
}

// ---------------------------------------------------------------------------
// Launch
// ---------------------------------------------------------------------------
extern "C" void kernel_launch(void* const* d_in, const int* in_sizes, int n_in,
                              void* d_out, int out_size)
{
    const float* seq_out = (const float*)d_in[0];
    const int* attn_mask = (const int*)d_in[1];
    const int* lang_raw = (const int*)d_in[2];
    const float* W1 = (const float*)d_in[3];
    const float* b1 = (const float*)d_in[4];
    const float* ln_g = (const float*)d_in[5];
    const float* ln_b = (const float*)d_in[6];
    const float* W2 = (const float*)d_in[7];
    const float* b2 = (const float*)d_in[8];
    const float* Wih_f = (const float*)d_in[9];
    const float* Whh_f = (const float*)d_in[10];
    const float* b_f = (const float*)d_in[11];
    const float* Wih_b = (const float*)d_in[12];
    const float* Whh_b = (const float*)d_in[13];
    const float* b_b = (const float*)d_in[14];
    const float* Wp = (const float*)d_in[15];
    const float* bp = (const float*)d_in[16];
    float* out = (float*)d_out;

    float* h1;       cudaGetSymbolAddress((void**)&h1, g_h1);
    float* adapted;  cudaGetSymbolAddress((void**)&adapted, g_adapted);
    float* gates_f;  cudaGetSymbolAddress((void**)&gates_f, g_gates_f);
    float* gates_b;  cudaGetSymbolAddress((void**)&gates_b, g_gates_b);
    float* ys;       cudaGetSymbolAddress((void**)&ys, g_ys);
    float* Wt1;      cudaGetSymbolAddress((void**)&Wt1, g_Wt1);
    float* Wt2;      cudaGetSymbolAddress((void**)&Wt2, g_Wt2);
    void* h_ptr;     cudaGetSymbolAddress(&h_ptr, g_h);
    void* bar_ptr;   cudaGetSymbolAddress(&bar_ptr, g_bar);

    cudaFuncSetAttribute(lstm_kernel,
                         cudaFuncAttributeMaxDynamicSharedMemorySize,
                         LSTM_SMEM_BYTES);

    cudaMemsetAsync(h_ptr, 0, sizeof(float) * 2 * 2 * HL * BATCH);
    cudaMemsetAsync(bar_ptr, 0, sizeof(unsigned) * 2);

    // 0) normalize language ids + transpose adapter weights
    lang_normalize_kernel<<<1, 32>>>(lang_raw);
    transpose_w_kernel<<<dim3(32, 32, NLANG), 256>>>(W1, Wt1);
    transpose_w_kernel<<<dim3(32, 32, NLANG), 256>>>(W2, Wt2);
    // 1) adapter GEMM1 (3xtf32 mma.sync, 512 thr)
    mma_adapter_kernel<<<dim3(HID / 128, SEQ / 128, BATCH), 512>>>(
        seq_out, Wt1, b1, h1);
    // 2) LN + ReLU
    ln_relu_kernel<<<BATCH * SEQ, 256>>>(h1, ln_g, ln_b);
    // 3) adapter GEMM2 (3xtf32 mma.sync, 512 thr)
    mma_adapter_kernel<<<dim3(HID / 128, SEQ / 128, BATCH), 512>>>(
        h1, Wt2, b2, adapted);
    // 4) input-gate precompute, both directions
    mma_nt_kernel<<<dim3(4 * HL / 128, BATCH * SEQ / 128), 512>>>(
        adapted, Wih_f, b_f, gates_f, HID, 4 * HL);
    mma_nt_kernel<<<dim3(4 * HL / 128, BATCH * SEQ / 128), 512>>>(
        adapted, Wih_b, b_b, gates_b, HID, 4 * HL);
    // 5) persistent BiLSTM
    lstm_kernel<<<dim3(64, 2), 256, LSTM_SMEM_BYTES>>>(
        gates_f, gates_b, Whh_f, Whh_b, attn_mask, ys);
    // 6) projection (fp32 SIMT)
    nt_gemm_kernel<<<dim3(EOUT / TS_BN, BATCH * SEQ / TS_BM), 256>>>(
        ys, Wp, bp, out, 2 * HL, EOUT);
}

// round 12
// speedup vs baseline: 1.0779x; 1.0779x over previous
#include <cuda_runtime.h>
#include <cuda_bf16.h>
#include <cstdint>

// Problem constants
#define BATCH 32
#define SEQ   256
#define HID   1024
#define HL    512
#define EOUT  256
#define NLANG 5

typedef unsigned long long ull;

// ---------------------------------------------------------------------------
// Scratch (device globals — no allocation allowed)
// ---------------------------------------------------------------------------
__device__ float g_h1[BATCH * SEQ * HID];
__device__ float g_adapted[BATCH * SEQ * HID];
__device__ float g_gates_f[BATCH * SEQ * 4 * HL];
__device__ float g_gates_b[BATCH * SEQ * 4 * HL];
__device__ float g_ys[BATCH * SEQ * 2 * HL];
__device__ float g_h[2][2][HL][BATCH];     // dir, pingpong, UNIT, BATCH
__device__ unsigned g_bar[2];
__device__ int   g_lang[BATCH];
__device__ float g_Wt1[NLANG * HID * HID];
__device__ float g_Wt2[NLANG * HID * HID];

// ---------------------------------------------------------------------------
// tf32 split + mma.sync helpers
// ---------------------------------------------------------------------------
__device__ __forceinline__ void tf32_split(float x, uint32_t& hi, uint32_t& lo)
{
    uint32_t h;
    asm("cvt.rna.tf32.f32 %0, %1;" : "=r"(h) : "f"(x));
    float r = x - __uint_as_float(h);
    uint32_t l;
    asm("cvt.rna.tf32.f32 %0, %1;" : "=r"(l) : "f"(r));
    hi = h; lo = l;
}

__device__ __forceinline__ void mma8(float* d, const uint32_t* a, const uint32_t* b)
{
    asm volatile(
        "mma.sync.aligned.m16n8k8.row.col.f32.tf32.tf32.f32 "
        "{%0,%1,%2,%3}, {%4,%5,%6,%7}, {%8,%9}, {%0,%1,%2,%3};"
        : "+f"(d[0]), "+f"(d[1]), "+f"(d[2]), "+f"(d[3])
        : "r"(a[0]), "r"(a[1]), "r"(a[2]), "r"(a[3]), "r"(b[0]), "r"(b[1]));
}

__device__ __forceinline__ void ffma2(ull& d, ull a, ull b)
{
    asm("fma.rn.f32x2 %0, %1, %2, %0;" : "+l"(d) : "l"(a), "l"(b));
}

// ---------------------------------------------------------------------------
// 3xtf32 NT GEMM body: C[128,128] = A[128,K] @ B[128,K]^T + bias
// 256 threads, 8 warps (4 along M x 2 along N), warp tile 32x64.
// hi/lo tf32 parts packed as float2 -> one LDS.64 per fragment pair.
// Row stride 132 float2: per-half-warp conflict-free fragment loads.
// ---------------------------------------------------------------------------
#define BKC 16
#define MM_PAD2 132

__device__ __forceinline__ void mma_nt_body(
    const float* __restrict__ At, int lda,
    const float* __restrict__ Bt, int ldb,
    const float* __restrict__ bias_t,
    float* __restrict__ Ct, int ldc,
    int K)
{
    __shared__ float2 As2[BKC][MM_PAD2];
    __shared__ float2 Bs2[BKC][MM_PAD2];

    int tid = threadIdx.x;
    int lane = tid & 31, wid = tid >> 5;
    int warpM = wid & 3, warpN = wid >> 2;
    int m0 = warpM * 32, n0w = warpN * 64;
    int g = lane >> 2, t4 = lane & 3;

    // staging: thread handles row r, k-range cq..cq+7
    int r = tid >> 1, cq = (tid & 1) * 8;

    float acc[2][8][4];
#pragma unroll
    for (int mi = 0; mi < 2; mi++)
#pragma unroll
        for (int ni = 0; ni < 8; ni++)
#pragma unroll
            for (int q = 0; q < 4; q++) acc[mi][ni][q] = 0.f;

    float4 pa0 = *(const float4*)(At + (size_t)r * lda + cq);
    float4 pa1 = *(const float4*)(At + (size_t)r * lda + cq + 4);
    float4 pb0 = *(const float4*)(Bt + (size_t)r * ldb + cq);
    float4 pb1 = *(const float4*)(Bt + (size_t)r * ldb + cq + 4);

    int nch = K >> 4;
    for (int c = 0; c < nch; ++c) {
        __syncthreads();
        {
            float av[8] = {pa0.x, pa0.y, pa0.z, pa0.w, pa1.x, pa1.y, pa1.z, pa1.w};
            float bv[8] = {pb0.x, pb0.y, pb0.z, pb0.w, pb1.x, pb1.y, pb1.z, pb1.w};
#pragma unroll
            for (int i = 0; i < 8; i++) {
                uint32_t h, l;
                tf32_split(av[i], h, l);
                As2[cq + i][r] = make_float2(__uint_as_float(h), __uint_as_float(l));
                tf32_split(bv[i], h, l);
                Bs2[cq + i][r] = make_float2(__uint_as_float(h), __uint_as_float(l));
            }
        }
        __syncthreads();
        if (c + 1 < nch) {
            int k0 = (c + 1) * BKC;
            pa0 = *(const float4*)(At + (size_t)r * lda + k0 + cq);
            pa1 = *(const float4*)(At + (size_t)r * lda + k0 + cq + 4);
            pb0 = *(const float4*)(Bt + (size_t)r * ldb + k0 + cq);
            pb1 = *(const float4*)(Bt + (size_t)r * ldb + k0 + cq + 4);
        }
#pragma unroll
        for (int ks = 0; ks < BKC; ks += 8) {
            uint32_t ah[2][4], al[2][4];
#pragma unroll
            for (int mi = 0; mi < 2; mi++) {
                int m = m0 + mi * 16;
                float2 a0 = As2[ks + t4][m + g];
                float2 a1 = As2[ks + t4][m + g + 8];
                float2 a2 = As2[ks + t4 + 4][m + g];
                float2 a3 = As2[ks + t4 + 4][m + g + 8];
                ah[mi][0] = __float_as_uint(a0.x); al[mi][0] = __float_as_uint(a0.y);
                ah[mi][1] = __float_as_uint(a1.x); al[mi][1] = __float_as_uint(a1.y);
                ah[mi][2] = __float_as_uint(a2.x); al[mi][2] = __float_as_uint(a2.y);
                ah[mi][3] = __float_as_uint(a3.x); al[mi][3] = __float_as_uint(a3.y);
            }
#pragma unroll
            for (int ni = 0; ni < 8; ni++) {
                int n = n0w + ni * 8 + g;
                float2 b0 = Bs2[ks + t4][n];
                float2 b1 = Bs2[ks + t4 + 4][n];
                uint32_t bh[2], bl[2];
                bh[0] = __float_as_uint(b0.x); bl[0] = __float_as_uint(b0.y);
                bh[1] = __float_as_uint(b1.x); bl[1] = __float_as_uint(b1.y);
#pragma unroll
                for (int mi = 0; mi < 2; mi++) {
                    mma8(acc[mi][ni], ah[mi], bh);
                    mma8(acc[mi][ni], ah[mi], bl);
                    mma8(acc[mi][ni], al[mi], bh);
                }
            }
        }
    }

#pragma unroll
    for (int mi = 0; mi < 2; mi++) {
#pragma unroll
        for (int ni = 0; ni < 8; ni++) {
            int row0 = m0 + mi * 16 + g;
            int col = n0w + ni * 8 + 2 * t4;
            float2 b2 = *(const float2*)&bias_t[col];
            float2 o0 = {acc[mi][ni][0] + b2.x, acc[mi][ni][1] + b2.y};
            float2 o1 = {acc[mi][ni][2] + b2.x, acc[mi][ni][3] + b2.y};
            *(float2*)&Ct[(size_t)row0 * ldc + col] = o0;
            *(float2*)&Ct[(size_t)(row0 + 8) * ldc + col] = o1;
        }
    }
}

__global__ void __launch_bounds__(256, 2) mma_adapter_kernel(
    const float* __restrict__ Abase, const float* __restrict__ Wt,
    const float* __restrict__ ball, float* __restrict__ Cbase)
{
    int b = blockIdx.z;
    int l = g_lang[b];
    const float* At = Abase + (size_t)b * SEQ * HID + (size_t)blockIdx.y * 128 * HID;
    const float* Bt = Wt + (size_t)l * HID * HID + (size_t)blockIdx.x * 128 * HID;
    const float* bias_t = ball + (size_t)l * HID + blockIdx.x * 128;
    float* Ct = Cbase + (size_t)b * SEQ * HID + (size_t)blockIdx.y * 128 * HID
              + blockIdx.x * 128;
    mma_nt_body(At, HID, Bt, HID, bias_t, Ct, HID, HID);
}

__global__ void __launch_bounds__(256, 2) mma_nt_kernel(
    const float* __restrict__ A, const float* __restrict__ B,
    const float* __restrict__ bias, float* __restrict__ C, int K, int ldc)
{
    const float* At = A + (size_t)blockIdx.y * 128 * K;
    const float* Bt = B + (size_t)blockIdx.x * 128 * K;
    const float* bias_t = bias + blockIdx.x * 128;
    float* Ct = C + (size_t)blockIdx.y * 128 * ldc + blockIdx.x * 128;
    mma_nt_body(At, K, Bt, K, bias_t, Ct, ldc, K);
}

// ---------------------------------------------------------------------------
// W transpose: Wt[l][n][k] = W[l][k][n]
// ---------------------------------------------------------------------------
__global__ void __launch_bounds__(256) transpose_w_kernel(
    const float* __restrict__ W, float* __restrict__ Wt)
{
    __shared__ float tile[32][33];
    int l = blockIdx.z;
    int k0 = blockIdx.y * 32, n0 = blockIdx.x * 32;
    const float* Win = W + (size_t)l * HID * HID;
    float* Wout = Wt + (size_t)l * HID * HID;
    int x = threadIdx.x & 31, y = (threadIdx.x >> 5) * 4;
#pragma unroll
    for (int i = 0; i < 4; i++)
        tile[y + i][x] = Win[(size_t)(k0 + y + i) * HID + n0 + x];
    __syncthreads();
#pragma unroll
    for (int i = 0; i < 4; i++)
        Wout[(size_t)(n0 + y + i) * HID + k0 + x] = tile[x][y + i];
}

// ---------------------------------------------------------------------------
// Language-id normalization (dtype-robust)
// ---------------------------------------------------------------------------
__global__ void lang_normalize_kernel(const int* __restrict__ raw)
{
    __shared__ int first[32];
    int t = threadIdx.x;
    first[t] = raw[t];
    __syncwarp();
    bool odd_zero = true;
#pragma unroll
    for (int i = 1; i < 32; i += 2) odd_zero &= (first[i] == 0);
    int v = odd_zero ? raw[2 * t] : first[t];
    v = v < 0 ? 0 : (v >= NLANG ? NLANG - 1 : v);
    g_lang[t] = v;
}

// ---------------------------------------------------------------------------
// fp32 SIMT NT GEMM (projection only)
// ---------------------------------------------------------------------------
#define TS_BM 128
#define TS_BN 64
#define TS_BK 16

__global__ void __launch_bounds__(256) nt_gemm_kernel(
    const float* __restrict__ A, const float* __restrict__ Bm,
    const float* __restrict__ bias, float* __restrict__ C,
    int K, int ldc)
{
    __shared__ float As[TS_BK][TS_BM + 4];
    __shared__ float Bs[TS_BK][TS_BN];
    int row0 = blockIdx.y * TS_BM, col0 = blockIdx.x * TS_BN;
    int tid = threadIdx.x;
    int tx = tid & 15, ty = tid >> 4;
    float acc[8][4];
#pragma unroll
    for (int i = 0; i < 8; i++)
#pragma unroll
        for (int j = 0; j < 4; j++) acc[i][j] = 0.f;

    for (int k0 = 0; k0 < K; k0 += TS_BK) {
#pragma unroll
        for (int q = 0; q < 2; ++q) {
            int slot = tid + q * 256;
            int rr = slot >> 2;
            int kk = (slot & 3) * 4;
            float4 v = *(const float4*)&A[(size_t)(row0 + rr) * K + k0 + kk];
            As[kk + 0][rr] = v.x; As[kk + 1][rr] = v.y;
            As[kk + 2][rr] = v.z; As[kk + 3][rr] = v.w;
        }
        {
            int n = tid >> 2;
            int kk4 = (tid & 3) * 4;
            float4 v = *(const float4*)&Bm[(size_t)(col0 + n) * K + k0 + kk4];
            Bs[kk4 + 0][n] = v.x; Bs[kk4 + 1][n] = v.y;
            Bs[kk4 + 2][n] = v.z; Bs[kk4 + 3][n] = v.w;
        }
        __syncthreads();
#pragma unroll
        for (int kk = 0; kk < TS_BK; ++kk) {
            float a[8];
#pragma unroll
            for (int i = 0; i < 8; i++) a[i] = As[kk][ty * 8 + i];
            float4 bv = *(const float4*)&Bs[kk][tx * 4];
#pragma unroll
            for (int i = 0; i < 8; i++) {
                acc[i][0] += a[i] * bv.x; acc[i][1] += a[i] * bv.y;
                acc[i][2] += a[i] * bv.z; acc[i][3] += a[i] * bv.w;
            }
        }
        __syncthreads();
    }
    float4 bb = *(const float4*)&bias[col0 + tx * 4];
#pragma unroll
    for (int i = 0; i < 8; i++) {
        float4 o;
        o.x = acc[i][0] + bb.x; o.y = acc[i][1] + bb.y;
        o.z = acc[i][2] + bb.z; o.w = acc[i][3] + bb.w;
        *(float4*)&C[(size_t)(row0 + ty * 8 + i) * ldc + col0 + tx * 4] = o;
    }
}

// ---------------------------------------------------------------------------
// LayerNorm (biased var) + ReLU, in place
// ---------------------------------------------------------------------------
__global__ void __launch_bounds__(256) ln_relu_kernel(
    float* __restrict__ h, const float* __restrict__ ln_g_all,
    const float* __restrict__ ln_b_all)
{
    int row = blockIdx.x;
    int b = row >> 8;
    int l = g_lang[b];
    float4* x = (float4*)(h + (size_t)row * HID);
    float4 v = x[threadIdx.x];
    float s = v.x + v.y + v.z + v.w;
    float ss = v.x * v.x + v.y * v.y + v.z * v.z + v.w * v.w;
#pragma unroll
    for (int o = 16; o; o >>= 1) {
        s += __shfl_xor_sync(0xffffffffu, s, o);
        ss += __shfl_xor_sync(0xffffffffu, ss, o);
    }
    __shared__ float rs[8], rss[8];
    __shared__ float smean, sinv;
    int w = threadIdx.x >> 5;
    if ((threadIdx.x & 31) == 0) { rs[w] = s; rss[w] = ss; }
    __syncthreads();
    if (threadIdx.x == 0) {
        float S = 0.f, SS = 0.f;
#pragma unroll
        for (int i = 0; i < 8; i++) { S += rs[i]; SS += rss[i]; }
        float mean = S * (1.f / 1024.f);
        float var = SS * (1.f / 1024.f) - mean * mean;
        smean = mean;
        sinv = rsqrtf(var + 1e-5f);
    }
    __syncthreads();
    float mean = smean, inv = sinv;
    float4 g4 = *((const float4*)(ln_g_all + (size_t)l * HID) + threadIdx.x);
    float4 b4 = *((const float4*)(ln_b_all + (size_t)l * HID) + threadIdx.x);
    v.x = fmaxf((v.x - mean) * inv * g4.x + b4.x, 0.f);
    v.y = fmaxf((v.y - mean) * inv * g4.y + b4.y, 0.f);
    v.z = fmaxf((v.z - mean) * inv * g4.z + b4.z, 0.f);
    v.w = fmaxf((v.w - mean) * inv * g4.w + b4.w, 0.f);
    x[threadIdx.x] = v;
}

// ---------------------------------------------------------------------------
// Persistent BiLSTM — register-resident Whh + broadcast h + warp-local staging.
// ---------------------------------------------------------------------------
#define LSTM_HS_FLOATS (512 * 32)                 // 64 KB
#define LSTM_GS_FLOATS (8 * 32 * 36)              // 36 KB
#define LSTM_SMEM_BYTES ((LSTM_HS_FLOATS + LSTM_GS_FLOATS) * 4)

__device__ __forceinline__ float sigf(float x) { return 1.f / (1.f + expf(-x)); }

__global__ void __launch_bounds__(256, 1) lstm_kernel(
    const float* __restrict__ gates_f, const float* __restrict__ gates_b,
    const float* __restrict__ Whh_fw, const float* __restrict__ Whh_bw,
    const int* __restrict__ mask, float* __restrict__ ys)
{
    extern __shared__ float sm[];
    float* hs = sm;                                // [512][32]
    float* gsm = sm + LSTM_HS_FLOATS;              // [8][32][36]

    int tid = threadIdx.x;
    int dir = blockIdx.y;
    int u0 = blockIdx.x * 8;
    const float* Whh = dir ? Whh_bw : Whh_fw;
    const float* G = dir ? gates_b : gates_f;

    int lane = tid & 31, wp = tid >> 5;
    int grow = (lane >> 3) * HL + u0 + (lane & 7);
    int ks = wp * 64;

    float w_reg[64];
    {
        const float4* wsrc = (const float4*)(Whh + (size_t)grow * HL + ks);
#pragma unroll
        for (int j = 0; j < 16; j++) {
            float4 v = wsrc[j];
            w_reg[4 * j + 0] = v.x; w_reg[4 * j + 1] = v.y;
            w_reg[4 * j + 2] = v.z; w_reg[4 * j + 3] = v.w;
        }
    }

    int cu = tid >> 5;
    int cb = tid & 31;
    float c = 0.f;

    float* grow_out = gsm + (wp * 32 + lane) * 36;
    float4* hdst_seg = (float4*)(hs + ks * 32);

    for (int t = 0; t < SEQ; ++t) {
        int s = dir ? (SEQ - 1 - t) : t;
        int pp = t & 1;

        size_t gbase = ((size_t)(cb * SEQ + s)) * (4 * HL) + u0 + cu;
        float gi = G[gbase];
        float gf = G[gbase + 512];
        float gg = G[gbase + 1024];
        float go = G[gbase + 1536];
        int m = mask[cb * SEQ + s];

        {
            const float4* hsrc = (const float4*)(&g_h[dir][pp][0][0]) + ks * 8;
#pragma unroll
            for (int i = 0; i < 16; ++i)
                hdst_seg[lane + 32 * i] = __ldcg(hsrc + lane + 32 * i);
        }
        __syncwarp();

        ull acc[16];
#pragma unroll
        for (int j = 0; j < 16; j++) acc[j] = 0ull;
#pragma unroll
        for (int k = 0; k < 64; ++k) {
            uint32_t wb = __float_as_uint(w_reg[k]);
            ull w2;
            asm("mov.b64 %0, {%1, %1};" : "=l"(w2) : "r"(wb));
            const ulonglong2* hp = (const ulonglong2*)(hs + (ks + k) * 32);
#pragma unroll
            for (int j = 0; j < 8; ++j) {
                ulonglong2 h2 = hp[j];
                ffma2(acc[2 * j], w2, h2.x);
                ffma2(acc[2 * j + 1], w2, h2.y);
            }
        }
#pragma unroll
        for (int j = 0; j < 8; ++j) {
            ulonglong2 o;
            o.x = acc[2 * j]; o.y = acc[2 * j + 1];
            *(ulonglong2*)(grow_out + 4 * j) = o;
        }
        __syncthreads();

        {
            float ii = gi, ff = gf, g2 = gg, oo = go;
#pragma unroll
            for (int w = 0; w < 8; ++w) {
                const float* base = gsm + w * (32 * 36) + cb;
                ii += base[(0 * 8 + cu) * 36];
                ff += base[(1 * 8 + cu) * 36];
                g2 += base[(2 * 8 + cu) * 36];
                oo += base[(3 * 8 + cu) * 36];
            }
            float cn = sigf(ff) * c + sigf(ii) * tanhf(g2);
            float hn = sigf(oo) * tanhf(cn);
            float hold = hs[(u0 + cu) * 32 + cb];
            float hw = m ? hn : hold;
            c = m ? cn : c;
            g_h[dir][1 - pp][u0 + cu][cb] = hw;
            ys[((size_t)(cb * SEQ + s)) * (2 * HL) + dir * HL + u0 + cu] = m ? hn : 0.f;
        }

        __syncthreads();
        if (tid == 0) {
            __threadfence();
            atomicAdd(&g_bar[dir], 1u);
            unsigned tgt = 64u * (unsigned)(t + 1);
            while (*(volatile unsigned*)&g_bar[dir] < tgt) { }
            __threadfence();
        }
        __syncthreads();
    }
}

// ---------------------------------------------------------------------------
// Launch
// ---------------------------------------------------------------------------
extern "C" void kernel_launch(void* const* d_in, const int* in_sizes, int n_in,
                              void* d_out, int out_size)
{
    const float* seq_out = (const float*)d_in[0];
    const int* attn_mask = (const int*)d_in[1];
    const int* lang_raw = (const int*)d_in[2];
    const float* W1 = (const float*)d_in[3];
    const float* b1 = (const float*)d_in[4];
    const float* ln_g = (const float*)d_in[5];
    const float* ln_b = (const float*)d_in[6];
    const float* W2 = (const float*)d_in[7];
    const float* b2 = (const float*)d_in[8];
    const float* Wih_f = (const float*)d_in[9];
    const float* Whh_f = (const float*)d_in[10];
    const float* b_f = (const float*)d_in[11];
    const float* Wih_b = (const float*)d_in[12];
    const float* Whh_b = (const float*)d_in[13];
    const float* b_b = (const float*)d_in[14];
    const float* Wp = (const float*)d_in[15];
    const float* bp = (const float*)d_in[16];
    float* out = (float*)d_out;

    float* h1;       cudaGetSymbolAddress((void**)&h1, g_h1);
    float* adapted;  cudaGetSymbolAddress((void**)&adapted, g_adapted);
    float* gates_f;  cudaGetSymbolAddress((void**)&gates_f, g_gates_f);
    float* gates_b;  cudaGetSymbolAddress((void**)&gates_b, g_gates_b);
    float* ys;       cudaGetSymbolAddress((void**)&ys, g_ys);
    float* Wt1;      cudaGetSymbolAddress((void**)&Wt1, g_Wt1);
    float* Wt2;      cudaGetSymbolAddress((void**)&Wt2, g_Wt2);
    void* h_ptr;     cudaGetSymbolAddress(&h_ptr, g_h);
    void* bar_ptr;   cudaGetSymbolAddress(&bar_ptr, g_bar);

    cudaFuncSetAttribute(lstm_kernel,
                         cudaFuncAttributeMaxDynamicSharedMemorySize,
                         LSTM_SMEM_BYTES);

    cudaMemsetAsync(h_ptr, 0, sizeof(float) * 2 * 2 * HL * BATCH);
    cudaMemsetAsync(bar_ptr, 0, sizeof(unsigned) * 2);

    // 0) normalize language ids + transpose adapter weights
    lang_normalize_kernel<<<1, 32>>>(lang_raw);
    transpose_w_kernel<<<dim3(32, 32, NLANG), 256>>>(W1, Wt1);
    transpose_w_kernel<<<dim3(32, 32, NLANG), 256>>>(W2, Wt2);
    // 1) adapter GEMM1 (3xtf32 mma.sync, packed hi/lo)
    mma_adapter_kernel<<<dim3(HID / 128, SEQ / 128, BATCH), 256>>>(
        seq_out, Wt1, b1, h1);
    // 2) LN + ReLU
    ln_relu_kernel<<<BATCH * SEQ, 256>>>(h1, ln_g, ln_b);
    // 3) adapter GEMM2
    mma_adapter_kernel<<<dim3(HID / 128, SEQ / 128, BATCH), 256>>>(
        h1, Wt2, b2, adapted);
    // 4) input-gate precompute, both directions
    mma_nt_kernel<<<dim3(4 * HL / 128, BATCH * SEQ / 128), 256>>>(
        adapted, Wih_f, b_f, gates_f, HID, 4 * HL);
    mma_nt_kernel<<<dim3(4 * HL / 128, BATCH * SEQ / 128), 256>>>(
        adapted, Wih_b, b_b, gates_b, HID, 4 * HL);
    // 5) persistent BiLSTM
    lstm_kernel<<<dim3(64, 2), 256, LSTM_SMEM_BYTES>>>(
        gates_f, gates_b, Whh_f, Whh_b, attn_mask, ys);
    // 6) projection (fp32 SIMT)
    nt_gemm_kernel<<<dim3(EOUT / TS_BN, BATCH * SEQ / TS_BM), 256>>>(
        ys, Wp, bp, out, 2 * HL, EOUT);
}